// round 10
// baseline (speedup 1.0000x reference)
#include <cuda_runtime.h>
#include <math.h>
#include <stdint.h>

// Problem constants
#define Bc 4
#define Nc 8192
#define Ec 128
#define Hc 4
#define Dc 32
#define PADc 16
#define Wc 33
#define BHc 16
#define Mc (Bc * Nc)   // 32768 rows

// Scratch (device globals: no allocation allowed in kernel_launch)
__device__ float g_Q[(size_t)BHc * Nc * Dc];     // (B,H,N,D)
__device__ float g_K[(size_t)BHc * Nc * Dc];
__device__ float g_V[(size_t)BHc * Nc * Dc];
__device__ float g_ctx[(size_t)Mc * Ec];          // (B,N,E)

__device__ __forceinline__ uint32_t f2tf32(float x) {
    uint32_t r;
    asm("cvt.rna.tf32.f32 %0, %1;" : "=r"(r) : "f"(x));
    return r;
}

__device__ __forceinline__ uint32_t hi_bits(float x) {
    return __float_as_uint(x) & 0xFFFFE000u;
}

__device__ __forceinline__ void mma_tf32(
    float& c0, float& c1, float& c2, float& c3,
    uint32_t a0, uint32_t a1, uint32_t a2, uint32_t a3,
    uint32_t b0, uint32_t b1)
{
    asm volatile(
        "mma.sync.aligned.m16n8k8.row.col.f32.tf32.tf32.f32 "
        "{%0,%1,%2,%3}, {%4,%5,%6,%7}, {%8,%9}, {%0,%1,%2,%3};\n"
        : "+f"(c0), "+f"(c1), "+f"(c2), "+f"(c3)
        : "r"(a0), "r"(a1), "r"(a2), "r"(a3), "r"(b0), "r"(b1));
}

// ldmatrix x4: four 8x8 b16 matrices (= four 8x4 tf32 tiles).
// With stride-36-float rows: 8 rows x 4 banks -> all 32 banks, conflict-free.
__device__ __forceinline__ void ldsm_x4(
    uint32_t& r0, uint32_t& r1, uint32_t& r2, uint32_t& r3, uint32_t saddr)
{
    asm volatile("ldmatrix.sync.aligned.m8n8.x4.shared.b16 {%0,%1,%2,%3}, [%4];"
                 : "=r"(r0), "=r"(r1), "=r"(r2), "=r"(r3) : "r"(saddr));
}

// ---------------------------------------------------------------------------
// tf32 MMA GEMM core: C(128x128) = A(128x128) @ B(128x128)^T (+bias)
// 512 threads = 16 warps; warp grid 4(M) x 4(N); warp tile 32x32.
// acc = 32 regs/thread -> 3 blocks/SM (48 warps, 75% occ) at 128x128 tile
// economy (same staging traffic per MAC as the proven R8 core).
// smem stride 36; cvt to tf32 at staging; ldmatrix.x4 fragment loads.
// ---------------------------------------------------------------------------
#define GEMM_MMA_BODY(A_PTR, B_PTR, EPILOGUE)                                   \
    __shared__ uint32_t As[128 * 36];                                           \
    __shared__ uint32_t Bs[128 * 36];                                           \
    const int tid  = threadIdx.x;                                               \
    const int wid  = tid >> 5;                                                  \
    const int lane = tid & 31;                                                  \
    const int wm   = wid >> 2;       /* 0..3 */                                 \
    const int wn   = wid & 3;        /* 0..3 */                                 \
    const int gr   = lane >> 2;      /* 0..7 */                                 \
    const int gc   = lane & 3;       /* 0..3 */                                 \
    const int lm   = lane >> 3;      /* ldmatrix matrix idx 0..3 */             \
    const int lr   = lane & 7;       /* ldmatrix row-in-matrix */               \
    const int m0   = blockIdx.x * 128;                                          \
    const uint32_t asB = (uint32_t)__cvta_generic_to_shared(As);                \
    const uint32_t bsB = (uint32_t)__cvta_generic_to_shared(Bs);                \
    uint32_t aAddr[2], bAddr[2];                                                \
    _Pragma("unroll")                                                           \
    for (int i = 0; i < 2; i++)                                                 \
        aAddr[i] = asB + (((wm * 32 + i * 16 + (lm & 1) * 8 + lr) * 36          \
                           + (lm >> 1) * 4) << 2);                              \
    _Pragma("unroll")                                                           \
    for (int j2 = 0; j2 < 2; j2++)                                              \
        bAddr[j2] = bsB + (((wn * 32 + j2 * 16 + (lm >> 1) * 8 + lr) * 36       \
                            + (lm & 1) * 4) << 2);                              \
    float acc[2][4][4];                                                         \
    _Pragma("unroll")                                                           \
    for (int i = 0; i < 2; i++)                                                 \
        _Pragma("unroll")                                                       \
        for (int j = 0; j < 4; j++)                                             \
            _Pragma("unroll")                                                   \
            for (int e = 0; e < 4; e++) acc[i][j][e] = 0.f;                     \
    for (int k0 = 0; k0 < 128; k0 += 32) {                                      \
        _Pragma("unroll")                                                       \
        for (int l = 0; l < 2; l++) {                                           \
            int li = tid + l * 512;        /* 0..1023 */                        \
            int r  = li >> 3;              /* 0..127 */                         \
            int c4 = (li & 7) * 4;                                              \
            float4 va = *(const float4*)(A_PTR + (size_t)(m0 + r) * 128 + k0 + c4); \
            As[r * 36 + c4 + 0] = f2tf32(va.x);                                 \
            As[r * 36 + c4 + 1] = f2tf32(va.y);                                 \
            As[r * 36 + c4 + 2] = f2tf32(va.z);                                 \
            As[r * 36 + c4 + 3] = f2tf32(va.w);                                 \
            float4 vb = *(const float4*)(B_PTR + (size_t)r * 128 + k0 + c4);    \
            Bs[r * 36 + c4 + 0] = f2tf32(vb.x);                                 \
            Bs[r * 36 + c4 + 1] = f2tf32(vb.y);                                 \
            Bs[r * 36 + c4 + 2] = f2tf32(vb.z);                                 \
            Bs[r * 36 + c4 + 3] = f2tf32(vb.w);                                 \
        }                                                                       \
        __syncthreads();                                                        \
        _Pragma("unroll")                                                       \
        for (int kk = 0; kk < 32; kk += 8) {                                    \
            uint32_t af[2][4];                                                  \
            _Pragma("unroll")                                                   \
            for (int i = 0; i < 2; i++)                                         \
                ldsm_x4(af[i][0], af[i][1], af[i][2], af[i][3],                 \
                        aAddr[i] + kk * 4);                                     \
            uint32_t bf[4][2];                                                  \
            _Pragma("unroll")                                                   \
            for (int j2 = 0; j2 < 2; j2++)                                      \
                ldsm_x4(bf[2 * j2][0], bf[2 * j2][1],                           \
                        bf[2 * j2 + 1][0], bf[2 * j2 + 1][1],                   \
                        bAddr[j2] + kk * 4);                                    \
            _Pragma("unroll")                                                   \
            for (int i = 0; i < 2; i++)                                         \
                _Pragma("unroll")                                               \
                for (int j = 0; j < 4; j++)                                     \
                    mma_tf32(acc[i][j][0], acc[i][j][1], acc[i][j][2], acc[i][j][3], \
                             af[i][0], af[i][1], af[i][2], af[i][3],            \
                             bf[j][0], bf[j][1]);                               \
        }                                                                       \
        __syncthreads();                                                        \
    }                                                                           \
    EPILOGUE

// ---------------------------------------------------------------------------
// Kernel 1: fused QKV projection -> (B,H,N,D) scatter.  grid = (256, 3)
// ---------------------------------------------------------------------------
__global__ __launch_bounds__(512, 3) void qkv_mma(
    const float* __restrict__ q,
    const float* __restrict__ Wq, const float* __restrict__ bq,
    const float* __restrict__ Wk, const float* __restrict__ bk,
    const float* __restrict__ Wv, const float* __restrict__ bv)
{
    const int which = blockIdx.y;
    const float* __restrict__ Wm = (which == 0) ? Wq : ((which == 1) ? Wk : Wv);
    const float* __restrict__ bm = (which == 0) ? bq : ((which == 1) ? bk : bv);
    float* __restrict__ outp = (which == 0) ? g_Q : ((which == 1) ? g_K : g_V);

    GEMM_MMA_BODY(q, Wm,
    {
        _Pragma("unroll")
        for (int i = 0; i < 2; i++) {
            _Pragma("unroll")
            for (int e2 = 0; e2 < 2; e2++) {
                int m = m0 + wm * 32 + i * 16 + gr + e2 * 8;
                int b = m >> 13;
                int n = m & 8191;
                _Pragma("unroll")
                for (int j = 0; j < 4; j++) {
                    int col = wn * 32 + j * 8 + gc * 2;
                    int h = col >> 5;
                    int d = col & 31;
                    float2 v;
                    v.x = acc[i][j][e2 * 2 + 0] + bm[col];
                    v.y = acc[i][j][e2 * 2 + 1] + bm[col + 1];
                    *(float2*)(outp + ((size_t)(b * Hc + h) * Nc + n) * Dc + d) = v;
                }
            }
        }
    })
}

// ---------------------------------------------------------------------------
// Kernel 3: output projection. out = ctx @ Wo.T + bo -> d_out (B,N,E)
// ---------------------------------------------------------------------------
__global__ __launch_bounds__(512, 3) void out_mma(
    const float* __restrict__ Wo, const float* __restrict__ bo,
    float* __restrict__ outp)
{
    const float* __restrict__ ctxp = g_ctx;
    GEMM_MMA_BODY(ctxp, Wo,
    {
        _Pragma("unroll")
        for (int i = 0; i < 2; i++) {
            _Pragma("unroll")
            for (int e2 = 0; e2 < 2; e2++) {
                int m = m0 + wm * 32 + i * 16 + gr + e2 * 8;
                _Pragma("unroll")
                for (int j = 0; j < 4; j++) {
                    int col = wn * 32 + j * 8 + gc * 2;
                    float2 v;
                    v.x = acc[i][j][e2 * 2 + 0] + bo[col];
                    v.y = acc[i][j][e2 * 2 + 1] + bo[col + 1];
                    *(float2*)(outp + (size_t)m * 128 + col) = v;
                }
            }
        }
    })
}

// ---------------------------------------------------------------------------
// Kernel 2: warp-independent tensorized sliding-window attention (unchanged).
// Block = 128 queries (4 warps x 32 queries); each warp owns a dense
// 64-key window of its 32-query band. S = Q@Kwin^T via split-tf32 (exact
// scores); OOB keys zero-padded (score exactly 0, matching reference);
// out-of-band entries zeroed. Band-zero MMAs skipped. QK fragments loaded
// via ldmatrix (raw fp32 bits), hi/lo split in regs. Probs staged
// compactly in smem then stored warp-coalesced.
// grid = (N/128, BH), 128 threads.
// ---------------------------------------------------------------------------
#define QS 36     // Qs/Ks stride
#define VS 165    // Vt stride: 165 mod 32 = 5 -> conflict-free stores & loads
#define SS 68     // per-warp S stride: 68 mod 32 = 4

__global__ __launch_bounds__(128) void attn_mma(float* __restrict__ probs_out)
{
    extern __shared__ float sm[];
    float* Qs   = sm;                       // 128 x 36 raw fp32 (reused for probs)
    float* Ks   = Qs + 128 * QS;            // 160 x 36 raw fp32 (zero OOB)
    float* Vt   = Ks + 160 * QS;            // 32 x 165 tf32 transposed (zero OOB)
    float* Sall = Vt + 32 * VS;             // 4 warps x (32 x 68)

    const int tile = blockIdx.x;            // 0..63
    const int bh   = blockIdx.y;            // 0..15
    const int tid  = threadIdx.x;
    const int wid  = tid >> 5;              // 0..3
    const int lane = tid & 31;
    const int gr   = lane >> 2;
    const int gc   = lane & 3;
    const int lm   = lane >> 3;
    const int lr   = lane & 7;
    const int n0   = tile * 128;
    const int g0   = n0 - PADc;

    const float* __restrict__ Qg = g_Q + (size_t)bh * Nc * Dc;
    const float* __restrict__ Kg = g_K + (size_t)bh * Nc * Dc;
    const float* __restrict__ Vg = g_V + (size_t)bh * Nc * Dc;

    // Stage Q (128x32)
#pragma unroll
    for (int l = 0; l < 8; l++) {
        int idx = tid + l * 128;            // 0..1023
        int r   = idx >> 3;
        int c4  = (idx & 7) * 4;
        *(float4*)&Qs[r * QS + c4] = *(const float4*)(Qg + (size_t)(n0 + r) * 32 + c4);
    }
    // Stage K (160x32 raw, zero OOB) and V transposed (tf32, zero OOB)
#pragma unroll
    for (int l = 0; l < 10; l++) {
        int idx = tid + l * 128;            // 0..1279
        int r   = idx >> 3;                 // 0..159
        int c4  = (idx & 7) * 4;
        int grow = g0 + r;
        float4 kv = make_float4(0.f, 0.f, 0.f, 0.f);
        float4 vv = make_float4(0.f, 0.f, 0.f, 0.f);
        if (grow >= 0 && grow < Nc) {
            kv = *(const float4*)(Kg + (size_t)grow * 32 + c4);
            vv = *(const float4*)(Vg + (size_t)grow * 32 + c4);
        }
        *(float4*)&Ks[r * QS + c4] = kv;
        Vt[(c4 + 0) * VS + r] = __uint_as_float(f2tf32(vv.x));
        Vt[(c4 + 1) * VS + r] = __uint_as_float(f2tf32(vv.y));
        Vt[(c4 + 2) * VS + r] = __uint_as_float(f2tf32(vv.z));
        Vt[(c4 + 3) * VS + r] = __uint_as_float(f2tf32(vv.w));
    }
    __syncthreads();

    float* Sw = Sall + wid * (32 * SS);
    const int woff = wid * 32;              // warp's key-window offset in staged rows

    // ldmatrix addresses for QK fragments (raw fp32 bits)
    const uint32_t qsB = (uint32_t)__cvta_generic_to_shared(Qs);
    const uint32_t ksB = (uint32_t)__cvta_generic_to_shared(Ks);
    uint32_t qAddr[2], kAddr[4];
#pragma unroll
    for (int i = 0; i < 2; i++)
        qAddr[i] = qsB + (((woff + i * 16 + (lm & 1) * 8 + lr) * QS + (lm >> 1) * 4) << 2);
#pragma unroll
    for (int j2 = 0; j2 < 4; j2++)
        kAddr[j2] = ksB + (((woff + j2 * 16 + (lm >> 1) * 8 + lr) * QS + (lm & 1) * 4) << 2);

    // ---- QK^T: S(32x64) via split-tf32 (hh + hl + lh) ----
    // Band: row m uses cols [m, m+32]. Fragment block (i,j): i=0: j in [0,5];
    // i=1: j in [2,7]. Others provably zero.
    float acc[2][8][4];
#pragma unroll
    for (int i = 0; i < 2; i++)
#pragma unroll
        for (int j = 0; j < 8; j++)
#pragma unroll
            for (int e = 0; e < 4; e++) acc[i][j][e] = 0.f;

#pragma unroll
    for (int kk = 0; kk < 32; kk += 8) {
        uint32_t ah[2][4], al[2][4];
#pragma unroll
        for (int i = 0; i < 2; i++) {
            uint32_t raw[4];
            ldsm_x4(raw[0], raw[1], raw[2], raw[3], qAddr[i] + kk * 4);
#pragma unroll
            for (int e = 0; e < 4; e++) {
                float x = __uint_as_float(raw[e]);
                ah[i][e] = raw[e] & 0xFFFFE000u;
                al[i][e] = __float_as_uint(x - __uint_as_float(ah[i][e]));
            }
        }
        uint32_t bhf[8][2], blf[8][2];
#pragma unroll
        for (int j2 = 0; j2 < 4; j2++) {
            uint32_t raw[4];
            ldsm_x4(raw[0], raw[1], raw[2], raw[3], kAddr[j2] + kk * 4);
#pragma unroll
            for (int e = 0; e < 4; e++) {
                int j = 2 * j2 + (e >> 1);
                int s = e & 1;
                float y = __uint_as_float(raw[e]);
                bhf[j][s] = raw[e] & 0xFFFFE000u;
                blf[j][s] = __float_as_uint(y - __uint_as_float(bhf[j][s]));
            }
        }
#pragma unroll
        for (int i = 0; i < 2; i++)
#pragma unroll
            for (int j = 0; j < 8; j++) {
                if (i == 0 && j >= 6) continue;   // fully out-of-band
                if (i == 1 && j <= 1) continue;   // fully out-of-band
                mma_tf32(acc[i][j][0], acc[i][j][1], acc[i][j][2], acc[i][j][3],
                         al[i][0], al[i][1], al[i][2], al[i][3], bhf[j][0], bhf[j][1]);
                mma_tf32(acc[i][j][0], acc[i][j][1], acc[i][j][2], acc[i][j][3],
                         ah[i][0], ah[i][1], ah[i][2], ah[i][3], blf[j][0], blf[j][1]);
                mma_tf32(acc[i][j][0], acc[i][j][1], acc[i][j][2], acc[i][j][3],
                         ah[i][0], ah[i][1], ah[i][2], ah[i][3], bhf[j][0], bhf[j][1]);
            }
    }

    // Epilogue: scale in-band (0 <= c-m <= 32), zero out-of-band
    const float scale = 0.17677669529663687f;   // 1/sqrt(32)
#pragma unroll
    for (int i = 0; i < 2; i++) {
#pragma unroll
        for (int j = 0; j < 8; j++) {
            int c0 = j * 8 + gc * 2;
#pragma unroll
            for (int e2 = 0; e2 < 2; e2++) {
                int m = i * 16 + gr + e2 * 8;
                int w0 = c0 - m;
                float v0 = (w0 >= 0     && w0 <= 32) ? acc[i][j][e2 * 2 + 0] * scale : 0.f;
                float v1 = (w0 + 1 >= 0 && w0 + 1 <= 32) ? acc[i][j][e2 * 2 + 1] * scale : 0.f;
                float2 v; v.x = v0; v.y = v1;
                *(float2*)&Sw[m * SS + c0] = v;
            }
        }
    }
    __syncwarp();

    // ---- softmax per query (lane = local query m) ----
    float* Pc = Qs + wid * 32 * QS;          // dead Qs region; stride 33 scatter
    {
        const int m = lane;
        float* row = Sw + m * SS;
        float sc[33];
#pragma unroll
        for (int w = 0; w < 33; w++) sc[w] = row[m + w];
        float mx = sc[0];
#pragma unroll
        for (int w = 1; w < 33; w++) mx = fmaxf(mx, sc[w]);
        float ssum = 0.f;
#pragma unroll
        for (int w = 0; w < 33; w++) { sc[w] = __expf(sc[w] - mx); ssum += sc[w]; }
        const float rinv = 1.f / ssum;
#pragma unroll
        for (int w = 0; w < 33; w++) {
            float p = sc[w] * rinv;
            Pc[m * 33 + w] = p;
            row[m + w] = __uint_as_float(f2tf32(p));
        }
    }
    __syncwarp();

    // Warp-coalesced probs store: 32 queries x 33 floats contiguous in gmem.
    {
        float* gp = probs_out + ((size_t)bh * Nc + n0 + wid * 32) * Wc;
        const float4* Ps4 = (const float4*)Pc;
        float4* Gp4 = (float4*)gp;
#pragma unroll
        for (int i = lane; i < 264; i += 32)   // 1056 floats = 264 float4
            Gp4[i] = Ps4[i];
    }

    // ---- ctx = P(32x64) @ V(64x32) via tf32 MMA ----
    // Row block i uses P cols [i*16, i*16+47] -> i=0: kk8 in [0,5]; i=1: [2,7].
    float acc2[2][4][4];
#pragma unroll
    for (int i = 0; i < 2; i++)
#pragma unroll
        for (int j = 0; j < 4; j++)
#pragma unroll
            for (int e = 0; e < 4; e++) acc2[i][j][e] = 0.f;

#pragma unroll
    for (int kk8 = 0; kk8 < 8; kk8++) {
        const int kk = kk8 * 8;
        uint32_t bf[4][2];
#pragma unroll
        for (int j = 0; j < 4; j++) {
            int nb = (j * 8 + gr) * VS + woff + kk + gc;
            bf[j][0] = __float_as_uint(Vt[nb]);
            bf[j][1] = __float_as_uint(Vt[nb + 4]);
        }
#pragma unroll
        for (int i = 0; i < 2; i++) {
            if (i == 0 && kk8 >= 6) continue;   // P cols 48+ zero for rows 0..15
            if (i == 1 && kk8 <= 1) continue;   // P cols <16 zero for rows 16..31
            uint32_t af[4];
            int rb = (i * 16 + gr) * SS + kk + gc;
            af[0] = __float_as_uint(Sw[rb]);
            af[1] = __float_as_uint(Sw[rb + 8 * SS]);
            af[2] = __float_as_uint(Sw[rb + 4]);
            af[3] = __float_as_uint(Sw[rb + 8 * SS + 4]);
#pragma unroll
            for (int j = 0; j < 4; j++)
                mma_tf32(acc2[i][j][0], acc2[i][j][1], acc2[i][j][2], acc2[i][j][3],
                         af[0], af[1], af[2], af[3], bf[j][0], bf[j][1]);
        }
    }

    // Epilogue: ctx -> (B,N,E)
    const int b = bh >> 2;
    const int h = bh & 3;
#pragma unroll
    for (int i = 0; i < 2; i++) {
#pragma unroll
        for (int j = 0; j < 4; j++) {
            int d = j * 8 + gc * 2;
#pragma unroll
            for (int e2 = 0; e2 < 2; e2++) {
                int m = i * 16 + gr + e2 * 8;
                float2 v;
                v.x = acc2[i][j][e2 * 2 + 0];
                v.y = acc2[i][j][e2 * 2 + 1];
                *(float2*)(g_ctx + ((size_t)(b * Nc) + n0 + wid * 32 + m) * Ec + h * 32 + d) = v;
            }
        }
    }
}

// ---------------------------------------------------------------------------
extern "C" void kernel_launch(void* const* d_in, const int* in_sizes, int n_in,
                              void* d_out, int out_size)
{
    (void)in_sizes; (void)n_in; (void)out_size;
    const float* q  = (const float*)d_in[0];
    const float* Wq = (const float*)d_in[1];
    const float* bq = (const float*)d_in[2];
    const float* Wk = (const float*)d_in[3];
    const float* bk = (const float*)d_in[4];
    const float* Wv = (const float*)d_in[5];
    const float* bv = (const float*)d_in[6];
    const float* Wo = (const float*)d_in[7];
    const float* bo = (const float*)d_in[8];

    float* outp  = (float*)d_out;                         // (B,N,E)
    float* probs = outp + (size_t)Bc * Nc * Ec;           // (B,H,N,W)

    const int attn_smem = (128 * QS + 160 * QS + 32 * VS + 4 * 32 * SS) * 4; // 97408 B
    cudaFuncSetAttribute(attn_mma, cudaFuncAttributeMaxDynamicSharedMemorySize, attn_smem);

    qkv_mma<<<dim3(Mc / 128, 3), 512>>>(q, Wq, bq, Wk, bk, Wv, bv);
    attn_mma<<<dim3(Nc / 128, BHc), 128, attn_smem>>>(probs);
    out_mma<<<dim3(Mc / 128, 1), 512>>>(Wo, bo, outp);
}

// round 11
// speedup vs baseline: 2.0896x; 2.0896x over previous
#include <cuda_runtime.h>
#include <math.h>
#include <stdint.h>

// Problem constants
#define Bc 4
#define Nc 8192
#define Ec 128
#define Hc 4
#define Dc 32
#define PADc 16
#define Wc 33
#define BHc 16
#define Mc (Bc * Nc)   // 32768 rows

// Scratch (device globals: no allocation allowed in kernel_launch)
__device__ float g_Q[(size_t)BHc * Nc * Dc];     // (B,H,N,D)
__device__ float g_K[(size_t)BHc * Nc * Dc];
__device__ float g_V[(size_t)BHc * Nc * Dc];
__device__ float g_ctx[(size_t)Mc * Ec];          // (B,N,E)

__device__ __forceinline__ uint32_t f2tf32(float x) {
    uint32_t r;
    asm("cvt.rna.tf32.f32 %0, %1;" : "=r"(r) : "f"(x));
    return r;
}

__device__ __forceinline__ uint32_t hi_bits(float x) {
    return __float_as_uint(x) & 0xFFFFE000u;
}

__device__ __forceinline__ void mma_tf32(
    float& c0, float& c1, float& c2, float& c3,
    uint32_t a0, uint32_t a1, uint32_t a2, uint32_t a3,
    uint32_t b0, uint32_t b1)
{
    asm volatile(
        "mma.sync.aligned.m16n8k8.row.col.f32.tf32.tf32.f32 "
        "{%0,%1,%2,%3}, {%4,%5,%6,%7}, {%8,%9}, {%0,%1,%2,%3};\n"
        : "+f"(c0), "+f"(c1), "+f"(c2), "+f"(c3)
        : "r"(a0), "r"(a1), "r"(a2), "r"(a3), "r"(b0), "r"(b1));
}

// ldmatrix x4: four 8x8 b16 matrices (= four 8x4 tf32 tiles).
// With stride-36-float rows: 8 rows x 4 banks -> all 32 banks, conflict-free.
__device__ __forceinline__ void ldsm_x4(
    uint32_t& r0, uint32_t& r1, uint32_t& r2, uint32_t& r3, uint32_t saddr)
{
    asm volatile("ldmatrix.sync.aligned.m8n8.x4.shared.b16 {%0,%1,%2,%3}, [%4];"
                 : "=r"(r0), "=r"(r1), "=r"(r2), "=r"(r3) : "r"(saddr));
}

// ---------------------------------------------------------------------------
// tf32 MMA GEMM core: C(128x64) = A(128x128) @ B(64x128)^T tile (+bias).
// 256 threads = 8 warps; warp grid 4(M) x 2(N); warp tile 32x32.
// acc = 32 regs/thread; __launch_bounds__(256,3) -> 85-reg budget (no spill),
// 3 blocks/SM = 24 warps (37.5% occ). smem 27.6KB/block.
// smem stride 36; cvt to tf32 at staging; ldmatrix.x4 fragment loads.
// Column offset n1 = blockIdx.y * 64.
// ---------------------------------------------------------------------------
#define GEMM_MMA_BODY(A_PTR, B_PTR, EPILOGUE)                                   \
    __shared__ uint32_t As[128 * 36];                                           \
    __shared__ uint32_t Bs[64 * 36];                                            \
    const int tid  = threadIdx.x;                                               \
    const int wid  = tid >> 5;                                                  \
    const int lane = tid & 31;                                                  \
    const int wm   = wid >> 1;       /* 0..3 */                                 \
    const int wn   = wid & 1;        /* 0..1 */                                 \
    const int gr   = lane >> 2;      /* 0..7 */                                 \
    const int gc   = lane & 3;       /* 0..3 */                                 \
    const int lm   = lane >> 3;      /* ldmatrix matrix idx 0..3 */             \
    const int lr   = lane & 7;       /* ldmatrix row-in-matrix */               \
    const int m0   = blockIdx.x * 128;                                          \
    const int n1   = blockIdx.y * 64;                                           \
    const uint32_t asB = (uint32_t)__cvta_generic_to_shared(As);                \
    const uint32_t bsB = (uint32_t)__cvta_generic_to_shared(Bs);                \
    uint32_t aAddr[2], bAddr[2];                                                \
    _Pragma("unroll")                                                           \
    for (int i = 0; i < 2; i++)                                                 \
        aAddr[i] = asB + (((wm * 32 + i * 16 + (lm & 1) * 8 + lr) * 36          \
                           + (lm >> 1) * 4) << 2);                              \
    _Pragma("unroll")                                                           \
    for (int j2 = 0; j2 < 2; j2++)                                              \
        bAddr[j2] = bsB + (((wn * 32 + j2 * 16 + (lm >> 1) * 8 + lr) * 36       \
                            + (lm & 1) * 4) << 2);                              \
    float acc[2][4][4];                                                         \
    _Pragma("unroll")                                                           \
    for (int i = 0; i < 2; i++)                                                 \
        _Pragma("unroll")                                                       \
        for (int j = 0; j < 4; j++)                                             \
            _Pragma("unroll")                                                   \
            for (int e = 0; e < 4; e++) acc[i][j][e] = 0.f;                     \
    for (int k0 = 0; k0 < 128; k0 += 32) {                                      \
        _Pragma("unroll")                                                       \
        for (int l = 0; l < 4; l++) {     /* A: 128x32 = 1024 float4 */         \
            int li = tid + l * 256;                                             \
            int r  = li >> 3;             /* 0..127 */                          \
            int c4 = (li & 7) * 4;                                              \
            float4 va = *(const float4*)(A_PTR + (size_t)(m0 + r) * 128 + k0 + c4); \
            As[r * 36 + c4 + 0] = f2tf32(va.x);                                 \
            As[r * 36 + c4 + 1] = f2tf32(va.y);                                 \
            As[r * 36 + c4 + 2] = f2tf32(va.z);                                 \
            As[r * 36 + c4 + 3] = f2tf32(va.w);                                 \
        }                                                                       \
        _Pragma("unroll")                                                       \
        for (int l = 0; l < 2; l++) {     /* B: 64x32 = 512 float4 */           \
            int li = tid + l * 256;                                             \
            int r  = li >> 3;             /* 0..63 */                           \
            int c4 = (li & 7) * 4;                                              \
            float4 vb = *(const float4*)(B_PTR + (size_t)(n1 + r) * 128 + k0 + c4); \
            Bs[r * 36 + c4 + 0] = f2tf32(vb.x);                                 \
            Bs[r * 36 + c4 + 1] = f2tf32(vb.y);                                 \
            Bs[r * 36 + c4 + 2] = f2tf32(vb.z);                                 \
            Bs[r * 36 + c4 + 3] = f2tf32(vb.w);                                 \
        }                                                                       \
        __syncthreads();                                                        \
        _Pragma("unroll")                                                       \
        for (int kk = 0; kk < 32; kk += 8) {                                    \
            uint32_t af[2][4];                                                  \
            _Pragma("unroll")                                                   \
            for (int i = 0; i < 2; i++)                                         \
                ldsm_x4(af[i][0], af[i][1], af[i][2], af[i][3],                 \
                        aAddr[i] + kk * 4);                                     \
            uint32_t bf[4][2];                                                  \
            _Pragma("unroll")                                                   \
            for (int j2 = 0; j2 < 2; j2++)                                      \
                ldsm_x4(bf[2 * j2][0], bf[2 * j2][1],                           \
                        bf[2 * j2 + 1][0], bf[2 * j2 + 1][1],                   \
                        bAddr[j2] + kk * 4);                                    \
            _Pragma("unroll")                                                   \
            for (int i = 0; i < 2; i++)                                         \
                _Pragma("unroll")                                               \
                for (int j = 0; j < 4; j++)                                     \
                    mma_tf32(acc[i][j][0], acc[i][j][1], acc[i][j][2], acc[i][j][3], \
                             af[i][0], af[i][1], af[i][2], af[i][3],            \
                             bf[j][0], bf[j][1]);                               \
        }                                                                       \
        __syncthreads();                                                        \
    }                                                                           \
    EPILOGUE

// ---------------------------------------------------------------------------
// Kernel 1: fused QKV projection -> (B,H,N,D) scatter.
// grid = (Mc/128, 2, 3): x = row tile, y = 64-col half, z = which weight.
// ---------------------------------------------------------------------------
__global__ __launch_bounds__(256, 3) void qkv_mma(
    const float* __restrict__ q,
    const float* __restrict__ Wq, const float* __restrict__ bq,
    const float* __restrict__ Wk, const float* __restrict__ bk,
    const float* __restrict__ Wv, const float* __restrict__ bv)
{
    const int which = blockIdx.z;
    const float* __restrict__ Wm = (which == 0) ? Wq : ((which == 1) ? Wk : Wv);
    const float* __restrict__ bm = (which == 0) ? bq : ((which == 1) ? bk : bv);
    float* __restrict__ outp = (which == 0) ? g_Q : ((which == 1) ? g_K : g_V);

    GEMM_MMA_BODY(q, Wm,
    {
        _Pragma("unroll")
        for (int i = 0; i < 2; i++) {
            _Pragma("unroll")
            for (int e2 = 0; e2 < 2; e2++) {
                int m = m0 + wm * 32 + i * 16 + gr + e2 * 8;
                int b = m >> 13;
                int n = m & 8191;
                _Pragma("unroll")
                for (int j = 0; j < 4; j++) {
                    int col = n1 + wn * 32 + j * 8 + gc * 2;
                    int h = col >> 5;
                    int d = col & 31;
                    float2 v;
                    v.x = acc[i][j][e2 * 2 + 0] + bm[col];
                    v.y = acc[i][j][e2 * 2 + 1] + bm[col + 1];
                    *(float2*)(outp + ((size_t)(b * Hc + h) * Nc + n) * Dc + d) = v;
                }
            }
        }
    })
}

// ---------------------------------------------------------------------------
// Kernel 3: output projection. out = ctx @ Wo.T + bo -> d_out (B,N,E)
// grid = (Mc/128, 2)
// ---------------------------------------------------------------------------
__global__ __launch_bounds__(256, 3) void out_mma(
    const float* __restrict__ Wo, const float* __restrict__ bo,
    float* __restrict__ outp)
{
    const float* __restrict__ ctxp = g_ctx;
    GEMM_MMA_BODY(ctxp, Wo,
    {
        _Pragma("unroll")
        for (int i = 0; i < 2; i++) {
            _Pragma("unroll")
            for (int e2 = 0; e2 < 2; e2++) {
                int m = m0 + wm * 32 + i * 16 + gr + e2 * 8;
                _Pragma("unroll")
                for (int j = 0; j < 4; j++) {
                    int col = n1 + wn * 32 + j * 8 + gc * 2;
                    float2 v;
                    v.x = acc[i][j][e2 * 2 + 0] + bo[col];
                    v.y = acc[i][j][e2 * 2 + 1] + bo[col + 1];
                    *(float2*)(outp + (size_t)m * 128 + col) = v;
                }
            }
        }
    })
}

// ---------------------------------------------------------------------------
// Kernel 2: warp-independent tensorized sliding-window attention (R8 exact).
// Block = 128 queries (4 warps x 32 queries); each warp owns a dense
// 64-key window of its 32-query band. S = Q@Kwin^T via split-tf32 (exact
// scores); OOB keys zero-padded (score exactly 0, matching reference);
// out-of-band entries zeroed. Band-zero MMAs skipped. QK fragments loaded
// via ldmatrix (raw fp32 bits), hi/lo split in regs. Probs staged
// compactly in smem then stored warp-coalesced.
// grid = (N/128, BH), 128 threads.
// ---------------------------------------------------------------------------
#define QS 36     // Qs/Ks stride
#define VS 165    // Vt stride: 165 mod 32 = 5 -> conflict-free stores & loads
#define SS 68     // per-warp S stride: 68 mod 32 = 4

__global__ __launch_bounds__(128) void attn_mma(float* __restrict__ probs_out)
{
    extern __shared__ float sm[];
    float* Qs   = sm;                       // 128 x 36 raw fp32 (reused for probs)
    float* Ks   = Qs + 128 * QS;            // 160 x 36 raw fp32 (zero OOB)
    float* Vt   = Ks + 160 * QS;            // 32 x 165 tf32 transposed (zero OOB)
    float* Sall = Vt + 32 * VS;             // 4 warps x (32 x 68)

    const int tile = blockIdx.x;            // 0..63
    const int bh   = blockIdx.y;            // 0..15
    const int tid  = threadIdx.x;
    const int wid  = tid >> 5;              // 0..3
    const int lane = tid & 31;
    const int gr   = lane >> 2;
    const int gc   = lane & 3;
    const int lm   = lane >> 3;
    const int lr   = lane & 7;
    const int n0   = tile * 128;
    const int g0   = n0 - PADc;

    const float* __restrict__ Qg = g_Q + (size_t)bh * Nc * Dc;
    const float* __restrict__ Kg = g_K + (size_t)bh * Nc * Dc;
    const float* __restrict__ Vg = g_V + (size_t)bh * Nc * Dc;

    // Stage Q (128x32)
#pragma unroll
    for (int l = 0; l < 8; l++) {
        int idx = tid + l * 128;            // 0..1023
        int r   = idx >> 3;
        int c4  = (idx & 7) * 4;
        *(float4*)&Qs[r * QS + c4] = *(const float4*)(Qg + (size_t)(n0 + r) * 32 + c4);
    }
    // Stage K (160x32 raw, zero OOB) and V transposed (tf32, zero OOB)
#pragma unroll
    for (int l = 0; l < 10; l++) {
        int idx = tid + l * 128;            // 0..1279
        int r   = idx >> 3;                 // 0..159
        int c4  = (idx & 7) * 4;
        int grow = g0 + r;
        float4 kv = make_float4(0.f, 0.f, 0.f, 0.f);
        float4 vv = make_float4(0.f, 0.f, 0.f, 0.f);
        if (grow >= 0 && grow < Nc) {
            kv = *(const float4*)(Kg + (size_t)grow * 32 + c4);
            vv = *(const float4*)(Vg + (size_t)grow * 32 + c4);
        }
        *(float4*)&Ks[r * QS + c4] = kv;
        Vt[(c4 + 0) * VS + r] = __uint_as_float(f2tf32(vv.x));
        Vt[(c4 + 1) * VS + r] = __uint_as_float(f2tf32(vv.y));
        Vt[(c4 + 2) * VS + r] = __uint_as_float(f2tf32(vv.z));
        Vt[(c4 + 3) * VS + r] = __uint_as_float(f2tf32(vv.w));
    }
    __syncthreads();

    float* Sw = Sall + wid * (32 * SS);
    const int woff = wid * 32;              // warp's key-window offset in staged rows

    // ldmatrix addresses for QK fragments (raw fp32 bits)
    const uint32_t qsB = (uint32_t)__cvta_generic_to_shared(Qs);
    const uint32_t ksB = (uint32_t)__cvta_generic_to_shared(Ks);
    uint32_t qAddr[2], kAddr[4];
#pragma unroll
    for (int i = 0; i < 2; i++)
        qAddr[i] = qsB + (((woff + i * 16 + (lm & 1) * 8 + lr) * QS + (lm >> 1) * 4) << 2);
#pragma unroll
    for (int j2 = 0; j2 < 4; j2++)
        kAddr[j2] = ksB + (((woff + j2 * 16 + (lm >> 1) * 8 + lr) * QS + (lm & 1) * 4) << 2);

    // ---- QK^T: S(32x64) via split-tf32 (hh + hl + lh) ----
    // Band: row m uses cols [m, m+32]. Fragment block (i,j): i=0: j in [0,5];
    // i=1: j in [2,7]. Others provably zero.
    float acc[2][8][4];
#pragma unroll
    for (int i = 0; i < 2; i++)
#pragma unroll
        for (int j = 0; j < 8; j++)
#pragma unroll
            for (int e = 0; e < 4; e++) acc[i][j][e] = 0.f;

#pragma unroll
    for (int kk = 0; kk < 32; kk += 8) {
        uint32_t ah[2][4], al[2][4];
#pragma unroll
        for (int i = 0; i < 2; i++) {
            uint32_t raw[4];
            ldsm_x4(raw[0], raw[1], raw[2], raw[3], qAddr[i] + kk * 4);
#pragma unroll
            for (int e = 0; e < 4; e++) {
                float x = __uint_as_float(raw[e]);
                ah[i][e] = raw[e] & 0xFFFFE000u;
                al[i][e] = __float_as_uint(x - __uint_as_float(ah[i][e]));
            }
        }
        uint32_t bhf[8][2], blf[8][2];
#pragma unroll
        for (int j2 = 0; j2 < 4; j2++) {
            uint32_t raw[4];
            ldsm_x4(raw[0], raw[1], raw[2], raw[3], kAddr[j2] + kk * 4);
#pragma unroll
            for (int e = 0; e < 4; e++) {
                int j = 2 * j2 + (e >> 1);
                int s = e & 1;
                float y = __uint_as_float(raw[e]);
                bhf[j][s] = raw[e] & 0xFFFFE000u;
                blf[j][s] = __float_as_uint(y - __uint_as_float(bhf[j][s]));
            }
        }
#pragma unroll
        for (int i = 0; i < 2; i++)
#pragma unroll
            for (int j = 0; j < 8; j++) {
                if (i == 0 && j >= 6) continue;   // fully out-of-band
                if (i == 1 && j <= 1) continue;   // fully out-of-band
                mma_tf32(acc[i][j][0], acc[i][j][1], acc[i][j][2], acc[i][j][3],
                         al[i][0], al[i][1], al[i][2], al[i][3], bhf[j][0], bhf[j][1]);
                mma_tf32(acc[i][j][0], acc[i][j][1], acc[i][j][2], acc[i][j][3],
                         ah[i][0], ah[i][1], ah[i][2], ah[i][3], blf[j][0], blf[j][1]);
                mma_tf32(acc[i][j][0], acc[i][j][1], acc[i][j][2], acc[i][j][3],
                         ah[i][0], ah[i][1], ah[i][2], ah[i][3], bhf[j][0], bhf[j][1]);
            }
    }

    // Epilogue: scale in-band (0 <= c-m <= 32), zero out-of-band
    const float scale = 0.17677669529663687f;   // 1/sqrt(32)
#pragma unroll
    for (int i = 0; i < 2; i++) {
#pragma unroll
        for (int j = 0; j < 8; j++) {
            int c0 = j * 8 + gc * 2;
#pragma unroll
            for (int e2 = 0; e2 < 2; e2++) {
                int m = i * 16 + gr + e2 * 8;
                int w0 = c0 - m;
                float v0 = (w0 >= 0     && w0 <= 32) ? acc[i][j][e2 * 2 + 0] * scale : 0.f;
                float v1 = (w0 + 1 >= 0 && w0 + 1 <= 32) ? acc[i][j][e2 * 2 + 1] * scale : 0.f;
                float2 v; v.x = v0; v.y = v1;
                *(float2*)&Sw[m * SS + c0] = v;
            }
        }
    }
    __syncwarp();

    // ---- softmax per query (lane = local query m) ----
    float* Pc = Qs + wid * 32 * QS;          // dead Qs region; stride 33 scatter
    {
        const int m = lane;
        float* row = Sw + m * SS;
        float sc[33];
#pragma unroll
        for (int w = 0; w < 33; w++) sc[w] = row[m + w];
        float mx = sc[0];
#pragma unroll
        for (int w = 1; w < 33; w++) mx = fmaxf(mx, sc[w]);
        float ssum = 0.f;
#pragma unroll
        for (int w = 0; w < 33; w++) { sc[w] = __expf(sc[w] - mx); ssum += sc[w]; }
        const float rinv = 1.f / ssum;
#pragma unroll
        for (int w = 0; w < 33; w++) {
            float p = sc[w] * rinv;
            Pc[m * 33 + w] = p;
            row[m + w] = __uint_as_float(f2tf32(p));
        }
    }
    __syncwarp();

    // Warp-coalesced probs store: 32 queries x 33 floats contiguous in gmem.
    {
        float* gp = probs_out + ((size_t)bh * Nc + n0 + wid * 32) * Wc;
        const float4* Ps4 = (const float4*)Pc;
        float4* Gp4 = (float4*)gp;
#pragma unroll
        for (int i = lane; i < 264; i += 32)   // 1056 floats = 264 float4
            Gp4[i] = Ps4[i];
    }

    // ---- ctx = P(32x64) @ V(64x32) via tf32 MMA ----
    // Row block i uses P cols [i*16, i*16+47] -> i=0: kk8 in [0,5]; i=1: [2,7].
    float acc2[2][4][4];
#pragma unroll
    for (int i = 0; i < 2; i++)
#pragma unroll
        for (int j = 0; j < 4; j++)
#pragma unroll
            for (int e = 0; e < 4; e++) acc2[i][j][e] = 0.f;

#pragma unroll
    for (int kk8 = 0; kk8 < 8; kk8++) {
        const int kk = kk8 * 8;
        uint32_t bf[4][2];
#pragma unroll
        for (int j = 0; j < 4; j++) {
            int nb = (j * 8 + gr) * VS + woff + kk + gc;
            bf[j][0] = __float_as_uint(Vt[nb]);
            bf[j][1] = __float_as_uint(Vt[nb + 4]);
        }
#pragma unroll
        for (int i = 0; i < 2; i++) {
            if (i == 0 && kk8 >= 6) continue;   // P cols 48+ zero for rows 0..15
            if (i == 1 && kk8 <= 1) continue;   // P cols <16 zero for rows 16..31
            uint32_t af[4];
            int rb = (i * 16 + gr) * SS + kk + gc;
            af[0] = __float_as_uint(Sw[rb]);
            af[1] = __float_as_uint(Sw[rb + 8 * SS]);
            af[2] = __float_as_uint(Sw[rb + 4]);
            af[3] = __float_as_uint(Sw[rb + 8 * SS + 4]);
#pragma unroll
            for (int j = 0; j < 4; j++)
                mma_tf32(acc2[i][j][0], acc2[i][j][1], acc2[i][j][2], acc2[i][j][3],
                         af[0], af[1], af[2], af[3], bf[j][0], bf[j][1]);
        }
    }

    // Epilogue: ctx -> (B,N,E)
    const int b = bh >> 2;
    const int h = bh & 3;
#pragma unroll
    for (int i = 0; i < 2; i++) {
#pragma unroll
        for (int j = 0; j < 4; j++) {
            int d = j * 8 + gc * 2;
#pragma unroll
            for (int e2 = 0; e2 < 2; e2++) {
                int m = i * 16 + gr + e2 * 8;
                float2 v;
                v.x = acc2[i][j][e2 * 2 + 0];
                v.y = acc2[i][j][e2 * 2 + 1];
                *(float2*)(g_ctx + ((size_t)(b * Nc) + n0 + wid * 32 + m) * Ec + h * 32 + d) = v;
            }
        }
    }
}

// ---------------------------------------------------------------------------
extern "C" void kernel_launch(void* const* d_in, const int* in_sizes, int n_in,
                              void* d_out, int out_size)
{
    (void)in_sizes; (void)n_in; (void)out_size;
    const float* q  = (const float*)d_in[0];
    const float* Wq = (const float*)d_in[1];
    const float* bq = (const float*)d_in[2];
    const float* Wk = (const float*)d_in[3];
    const float* bk = (const float*)d_in[4];
    const float* Wv = (const float*)d_in[5];
    const float* bv = (const float*)d_in[6];
    const float* Wo = (const float*)d_in[7];
    const float* bo = (const float*)d_in[8];

    float* outp  = (float*)d_out;                         // (B,N,E)
    float* probs = outp + (size_t)Bc * Nc * Ec;           // (B,H,N,W)

    const int attn_smem = (128 * QS + 160 * QS + 32 * VS + 4 * 32 * SS) * 4; // 97408 B
    cudaFuncSetAttribute(attn_mma, cudaFuncAttributeMaxDynamicSharedMemorySize, attn_smem);

    qkv_mma<<<dim3(Mc / 128, 2, 3), 256>>>(q, Wq, bq, Wk, bk, Wv, bv);
    attn_mma<<<dim3(Nc / 128, BHc), 128, attn_smem>>>(probs);
    out_mma<<<dim3(Mc / 128, 2), 256>>>(Wo, bo, outp);
}

// round 13
// speedup vs baseline: 2.8394x; 1.3588x over previous
#include <cuda_runtime.h>
#include <cuda_fp16.h>
#include <math.h>
#include <stdint.h>

// Problem constants
#define Bc 4
#define Nc 8192
#define Ec 128
#define Hc 4
#define Dc 32
#define PADc 16
#define Wc 33
#define BHc 16
#define Mc (Bc * Nc)   // 32768 rows

// Scratch (device globals: no allocation allowed in kernel_launch)
__device__ float g_Q[(size_t)BHc * Nc * Dc];     // (B,H,N,D)
__device__ float g_K[(size_t)BHc * Nc * Dc];
__device__ float g_V[(size_t)BHc * Nc * Dc];
__device__ float g_ctx[(size_t)Mc * Ec];          // (B,N,E)

__device__ __forceinline__ uint32_t f2tf32(float x) {
    uint32_t r;
    asm("cvt.rna.tf32.f32 %0, %1;" : "=r"(r) : "f"(x));
    return r;
}

__device__ __forceinline__ uint32_t pack_h2(float a, float b) {
    __half2 h = __floats2half2_rn(a, b);   // a -> low half (first in memory)
    return *(uint32_t*)&h;
}

__device__ __forceinline__ void mma_tf32(
    float& c0, float& c1, float& c2, float& c3,
    uint32_t a0, uint32_t a1, uint32_t a2, uint32_t a3,
    uint32_t b0, uint32_t b1)
{
    asm volatile(
        "mma.sync.aligned.m16n8k8.row.col.f32.tf32.tf32.f32 "
        "{%0,%1,%2,%3}, {%4,%5,%6,%7}, {%8,%9}, {%0,%1,%2,%3};\n"
        : "+f"(c0), "+f"(c1), "+f"(c2), "+f"(c3)
        : "r"(a0), "r"(a1), "r"(a2), "r"(a3), "r"(b0), "r"(b1));
}

__device__ __forceinline__ void mma_f16(
    float& c0, float& c1, float& c2, float& c3,
    uint32_t a0, uint32_t a1, uint32_t a2, uint32_t a3,
    uint32_t b0, uint32_t b1)
{
    asm volatile(
        "mma.sync.aligned.m16n8k16.row.col.f32.f16.f16.f32 "
        "{%0,%1,%2,%3}, {%4,%5,%6,%7}, {%8,%9}, {%0,%1,%2,%3};\n"
        : "+f"(c0), "+f"(c1), "+f"(c2), "+f"(c3)
        : "r"(a0), "r"(a1), "r"(a2), "r"(a3), "r"(b0), "r"(b1));
}

__device__ __forceinline__ void ldsm_x4(
    uint32_t& r0, uint32_t& r1, uint32_t& r2, uint32_t& r3, uint32_t saddr)
{
    asm volatile("ldmatrix.sync.aligned.m8n8.x4.shared.b16 {%0,%1,%2,%3}, [%4];"
                 : "=r"(r0), "=r"(r1), "=r"(r2), "=r"(r3) : "r"(saddr));
}

// ---------------------------------------------------------------------------
// fp16 MMA GEMM core: C(128x128) = A(128x128) @ B(128x128)^T (+bias)
// 256 threads = 8 warps; warp grid 4(M) x 2(N); warp tile 32x64.
// fp16 inputs (11-bit mantissa rounding == tf32), f32 accumulation.
// Full-K staging in one pass (perfectly coalesced), then 8 barrier-free
// m16n8k16 steps. Row stride 136 halves (272 B): 16 B shift per row mod 128
// -> ldmatrix conflict-free.
// ---------------------------------------------------------------------------
#define HSTR 136                       // halves per smem row
#define HROW (HSTR * 2)                // bytes per smem row (272)
#define HB_OFF (128 * HROW)            // B tile offset (34816 B)
#define H_TOTAL (2 * 128 * HROW)       // 69632 B

#define GEMM_F16_BODY(A_PTR, B_PTR, EPILOGUE)                                   \
    extern __shared__ __align__(16) char smh[];                                 \
    const int tid  = threadIdx.x;                                               \
    const int wid  = tid >> 5;                                                  \
    const int lane = tid & 31;                                                  \
    const int wm   = wid >> 1;       /* 0..3 */                                 \
    const int wn   = wid & 1;        /* 0..1 */                                 \
    const int gr   = lane >> 2;      /* 0..7 */                                 \
    const int gc   = lane & 3;       /* 0..3 */                                 \
    const int lm   = lane >> 3;      /* ldmatrix matrix idx 0..3 */             \
    const int lr   = lane & 7;       /* ldmatrix row-in-matrix */               \
    const int m0   = blockIdx.x * 128;                                          \
    /* stage full 128x128 tiles as fp16 (coalesced: warp = 1 row = 256 B) */    \
    _Pragma("unroll")                                                           \
    for (int l = 0; l < 16; l++) {                                              \
        int li = tid + l * 256;        /* 0..4095 */                            \
        int r  = li >> 5;              /* 0..127 */                             \
        int c4 = (li & 31) * 4;        /* 0..124 */                             \
        float4 va = *(const float4*)(A_PTR + (size_t)(m0 + r) * 128 + c4);      \
        uint2 ua;                                                               \
        ua.x = pack_h2(va.x, va.y);                                             \
        ua.y = pack_h2(va.z, va.w);                                             \
        *(uint2*)(smh + (size_t)r * HROW + c4 * 2) = ua;                        \
        float4 vb = *(const float4*)(B_PTR + (size_t)r * 128 + c4);             \
        uint2 ub;                                                               \
        ub.x = pack_h2(vb.x, vb.y);                                             \
        ub.y = pack_h2(vb.z, vb.w);                                             \
        *(uint2*)(smh + HB_OFF + (size_t)r * HROW + c4 * 2) = ub;               \
    }                                                                           \
    __syncthreads();                                                            \
    const uint32_t asB = (uint32_t)__cvta_generic_to_shared(smh);               \
    const uint32_t bsB = asB + HB_OFF;                                          \
    uint32_t aAddr[2], bAddr[4];                                                \
    _Pragma("unroll")                                                           \
    for (int i = 0; i < 2; i++)                                                 \
        aAddr[i] = asB + ((wm * 32 + i * 16 + (lm & 1) * 8 + lr) * HSTR         \
                          + (lm >> 1) * 8) * 2;                                 \
    _Pragma("unroll")                                                           \
    for (int j2 = 0; j2 < 4; j2++)                                              \
        bAddr[j2] = bsB + ((wn * 64 + j2 * 16 + (lm >> 1) * 8 + lr) * HSTR      \
                           + (lm & 1) * 8) * 2;                                 \
    float acc[2][8][4];                                                         \
    _Pragma("unroll")                                                           \
    for (int i = 0; i < 2; i++)                                                 \
        _Pragma("unroll")                                                       \
        for (int j = 0; j < 8; j++)                                             \
            _Pragma("unroll")                                                   \
            for (int e = 0; e < 4; e++) acc[i][j][e] = 0.f;                     \
    _Pragma("unroll")                                                           \
    for (int k16 = 0; k16 < 128; k16 += 16) {                                   \
        uint32_t af[2][4];                                                      \
        _Pragma("unroll")                                                       \
        for (int i = 0; i < 2; i++)                                             \
            ldsm_x4(af[i][0], af[i][1], af[i][2], af[i][3],                     \
                    aAddr[i] + k16 * 2);                                        \
        uint32_t bf[8][2];                                                      \
        _Pragma("unroll")                                                       \
        for (int j2 = 0; j2 < 4; j2++)                                          \
            ldsm_x4(bf[2 * j2][0], bf[2 * j2][1],                               \
                    bf[2 * j2 + 1][0], bf[2 * j2 + 1][1],                       \
                    bAddr[j2] + k16 * 2);                                       \
        _Pragma("unroll")                                                       \
        for (int i = 0; i < 2; i++)                                             \
            _Pragma("unroll")                                                   \
            for (int j = 0; j < 8; j++)                                         \
                mma_f16(acc[i][j][0], acc[i][j][1], acc[i][j][2], acc[i][j][3], \
                        af[i][0], af[i][1], af[i][2], af[i][3],                 \
                        bf[j][0], bf[j][1]);                                    \
    }                                                                           \
    EPILOGUE

// ---------------------------------------------------------------------------
// Kernel 1: fused QKV projection -> (B,H,N,D) scatter.  grid = (256, 3)
// ---------------------------------------------------------------------------
__global__ __launch_bounds__(256, 2) void qkv_mma(
    const float* __restrict__ q,
    const float* __restrict__ Wq, const float* __restrict__ bq,
    const float* __restrict__ Wk, const float* __restrict__ bk,
    const float* __restrict__ Wv, const float* __restrict__ bv)
{
    const int which = blockIdx.y;
    const float* __restrict__ Wm = (which == 0) ? Wq : ((which == 1) ? Wk : Wv);
    const float* __restrict__ bm = (which == 0) ? bq : ((which == 1) ? bk : bv);
    float* __restrict__ outp = (which == 0) ? g_Q : ((which == 1) ? g_K : g_V);

    GEMM_F16_BODY(q, Wm,
    {
        _Pragma("unroll")
        for (int i = 0; i < 2; i++) {
            _Pragma("unroll")
            for (int e2 = 0; e2 < 2; e2++) {
                int m = m0 + wm * 32 + i * 16 + gr + e2 * 8;
                int b = m >> 13;
                int n = m & 8191;
                _Pragma("unroll")
                for (int j = 0; j < 8; j++) {
                    int col = wn * 64 + j * 8 + gc * 2;
                    int h = col >> 5;
                    int d = col & 31;
                    float2 v;
                    v.x = acc[i][j][e2 * 2 + 0] + bm[col];
                    v.y = acc[i][j][e2 * 2 + 1] + bm[col + 1];
                    *(float2*)(outp + ((size_t)(b * Hc + h) * Nc + n) * Dc + d) = v;
                }
            }
        }
    })
}

// ---------------------------------------------------------------------------
// Kernel 3: output projection. out = ctx @ Wo.T + bo -> d_out (B,N,E)
// ---------------------------------------------------------------------------
__global__ __launch_bounds__(256, 2) void out_mma(
    const float* __restrict__ Wo, const float* __restrict__ bo,
    float* __restrict__ outp)
{
    const float* __restrict__ ctxp = g_ctx;
    GEMM_F16_BODY(ctxp, Wo,
    {
        _Pragma("unroll")
        for (int i = 0; i < 2; i++) {
            _Pragma("unroll")
            for (int e2 = 0; e2 < 2; e2++) {
                int m = m0 + wm * 32 + i * 16 + gr + e2 * 8;
                _Pragma("unroll")
                for (int j = 0; j < 8; j++) {
                    int col = wn * 64 + j * 8 + gc * 2;
                    float2 v;
                    v.x = acc[i][j][e2 * 2 + 0] + bo[col];
                    v.y = acc[i][j][e2 * 2 + 1] + bo[col + 1];
                    *(float2*)(outp + (size_t)m * 128 + col) = v;
                }
            }
        }
    })
}

// ---------------------------------------------------------------------------
// Kernel 2: warp-independent tensorized sliding-window attention (R8 exact).
// Block = 128 queries (4 warps x 32 queries); each warp owns a dense
// 64-key window of its 32-query band. S = Q@Kwin^T via split-tf32 (exact
// scores); OOB keys zero-padded (score exactly 0, matching reference);
// out-of-band entries zeroed. Band-zero MMAs skipped. QK fragments loaded
// via ldmatrix (raw fp32 bits), hi/lo split in regs. Probs staged
// compactly in smem then stored warp-coalesced.
// grid = (N/128, BH), 128 threads.
// ---------------------------------------------------------------------------
#define QS 36     // Qs/Ks stride
#define VS 165    // Vt stride: 165 mod 32 = 5 -> conflict-free stores & loads
#define SS 68     // per-warp S stride: 68 mod 32 = 4

__global__ __launch_bounds__(128) void attn_mma(float* __restrict__ probs_out)
{
    extern __shared__ float sm[];
    float* Qs   = sm;                       // 128 x 36 raw fp32 (reused for probs)
    float* Ks   = Qs + 128 * QS;            // 160 x 36 raw fp32 (zero OOB)
    float* Vt   = Ks + 160 * QS;            // 32 x 165 tf32 transposed (zero OOB)
    float* Sall = Vt + 32 * VS;             // 4 warps x (32 x 68)

    const int tile = blockIdx.x;
    const int bh   = blockIdx.y;
    const int tid  = threadIdx.x;
    const int wid  = tid >> 5;
    const int lane = tid & 31;
    const int gr   = lane >> 2;
    const int gc   = lane & 3;
    const int lm   = lane >> 3;
    const int lr   = lane & 7;
    const int n0   = tile * 128;
    const int g0   = n0 - PADc;

    const float* __restrict__ Qg = g_Q + (size_t)bh * Nc * Dc;
    const float* __restrict__ Kg = g_K + (size_t)bh * Nc * Dc;
    const float* __restrict__ Vg = g_V + (size_t)bh * Nc * Dc;

#pragma unroll
    for (int l = 0; l < 8; l++) {
        int idx = tid + l * 128;
        int r   = idx >> 3;
        int c4  = (idx & 7) * 4;
        *(float4*)&Qs[r * QS + c4] = *(const float4*)(Qg + (size_t)(n0 + r) * 32 + c4);
    }
#pragma unroll
    for (int l = 0; l < 10; l++) {
        int idx = tid + l * 128;
        int r   = idx >> 3;
        int c4  = (idx & 7) * 4;
        int grow = g0 + r;
        float4 kv = make_float4(0.f, 0.f, 0.f, 0.f);
        float4 vv = make_float4(0.f, 0.f, 0.f, 0.f);
        if (grow >= 0 && grow < Nc) {
            kv = *(const float4*)(Kg + (size_t)grow * 32 + c4);
            vv = *(const float4*)(Vg + (size_t)grow * 32 + c4);
        }
        *(float4*)&Ks[r * QS + c4] = kv;
        Vt[(c4 + 0) * VS + r] = __uint_as_float(f2tf32(vv.x));
        Vt[(c4 + 1) * VS + r] = __uint_as_float(f2tf32(vv.y));
        Vt[(c4 + 2) * VS + r] = __uint_as_float(f2tf32(vv.z));
        Vt[(c4 + 3) * VS + r] = __uint_as_float(f2tf32(vv.w));
    }
    __syncthreads();

    float* Sw = Sall + wid * (32 * SS);
    const int woff = wid * 32;

    const uint32_t qsB = (uint32_t)__cvta_generic_to_shared(Qs);
    const uint32_t ksB = (uint32_t)__cvta_generic_to_shared(Ks);
    uint32_t qAddr[2], kAddr[4];
#pragma unroll
    for (int i = 0; i < 2; i++)
        qAddr[i] = qsB + (((woff + i * 16 + (lm & 1) * 8 + lr) * QS + (lm >> 1) * 4) << 2);
#pragma unroll
    for (int j2 = 0; j2 < 4; j2++)
        kAddr[j2] = ksB + (((woff + j2 * 16 + (lm >> 1) * 8 + lr) * QS + (lm & 1) * 4) << 2);

    float acc[2][8][4];
#pragma unroll
    for (int i = 0; i < 2; i++)
#pragma unroll
        for (int j = 0; j < 8; j++)
#pragma unroll
            for (int e = 0; e < 4; e++) acc[i][j][e] = 0.f;

#pragma unroll
    for (int kk = 0; kk < 32; kk += 8) {
        uint32_t ah[2][4], al[2][4];
#pragma unroll
        for (int i = 0; i < 2; i++) {
            uint32_t raw[4];
            ldsm_x4(raw[0], raw[1], raw[2], raw[3], qAddr[i] + kk * 4);
#pragma unroll
            for (int e = 0; e < 4; e++) {
                float x = __uint_as_float(raw[e]);
                ah[i][e] = raw[e] & 0xFFFFE000u;
                al[i][e] = __float_as_uint(x - __uint_as_float(ah[i][e]));
            }
        }
        uint32_t bhf[8][2], blf[8][2];
#pragma unroll
        for (int j2 = 0; j2 < 4; j2++) {
            uint32_t raw[4];
            ldsm_x4(raw[0], raw[1], raw[2], raw[3], kAddr[j2] + kk * 4);
#pragma unroll
            for (int e = 0; e < 4; e++) {
                int j = 2 * j2 + (e >> 1);
                int s = e & 1;
                float y = __uint_as_float(raw[e]);
                bhf[j][s] = raw[e] & 0xFFFFE000u;
                blf[j][s] = __float_as_uint(y - __uint_as_float(bhf[j][s]));
            }
        }
#pragma unroll
        for (int i = 0; i < 2; i++)
#pragma unroll
            for (int j = 0; j < 8; j++) {
                if (i == 0 && j >= 6) continue;   // fully out-of-band
                if (i == 1 && j <= 1) continue;   // fully out-of-band
                mma_tf32(acc[i][j][0], acc[i][j][1], acc[i][j][2], acc[i][j][3],
                         al[i][0], al[i][1], al[i][2], al[i][3], bhf[j][0], bhf[j][1]);
                mma_tf32(acc[i][j][0], acc[i][j][1], acc[i][j][2], acc[i][j][3],
                         ah[i][0], ah[i][1], ah[i][2], ah[i][3], blf[j][0], blf[j][1]);
                mma_tf32(acc[i][j][0], acc[i][j][1], acc[i][j][2], acc[i][j][3],
                         ah[i][0], ah[i][1], ah[i][2], ah[i][3], bhf[j][0], bhf[j][1]);
            }
    }

    const float scale = 0.17677669529663687f;   // 1/sqrt(32)
#pragma unroll
    for (int i = 0; i < 2; i++) {
#pragma unroll
        for (int j = 0; j < 8; j++) {
            int c0 = j * 8 + gc * 2;
#pragma unroll
            for (int e2 = 0; e2 < 2; e2++) {
                int m = i * 16 + gr + e2 * 8;
                int w0 = c0 - m;
                float v0 = (w0 >= 0     && w0 <= 32) ? acc[i][j][e2 * 2 + 0] * scale : 0.f;
                float v1 = (w0 + 1 >= 0 && w0 + 1 <= 32) ? acc[i][j][e2 * 2 + 1] * scale : 0.f;
                float2 v; v.x = v0; v.y = v1;
                *(float2*)&Sw[m * SS + c0] = v;
            }
        }
    }
    __syncwarp();

    float* Pc = Qs + wid * 32 * QS;          // dead Qs region; stride 33 scatter
    {
        const int m = lane;
        float* row = Sw + m * SS;
        float sc[33];
#pragma unroll
        for (int w = 0; w < 33; w++) sc[w] = row[m + w];
        float mx = sc[0];
#pragma unroll
        for (int w = 1; w < 33; w++) mx = fmaxf(mx, sc[w]);
        float ssum = 0.f;
#pragma unroll
        for (int w = 0; w < 33; w++) { sc[w] = __expf(sc[w] - mx); ssum += sc[w]; }
        const float rinv = 1.f / ssum;
#pragma unroll
        for (int w = 0; w < 33; w++) {
            float p = sc[w] * rinv;
            Pc[m * 33 + w] = p;
            row[m + w] = __uint_as_float(f2tf32(p));
        }
    }
    __syncwarp();

    {
        float* gp = probs_out + ((size_t)bh * Nc + n0 + wid * 32) * Wc;
        const float4* Ps4 = (const float4*)Pc;
        float4* Gp4 = (float4*)gp;
#pragma unroll
        for (int i = lane; i < 264; i += 32)   // 1056 floats = 264 float4
            Gp4[i] = Ps4[i];
    }

    float acc2[2][4][4];
#pragma unroll
    for (int i = 0; i < 2; i++)
#pragma unroll
        for (int j = 0; j < 4; j++)
#pragma unroll
            for (int e = 0; e < 4; e++) acc2[i][j][e] = 0.f;

#pragma unroll
    for (int kk8 = 0; kk8 < 8; kk8++) {
        const int kk = kk8 * 8;
        uint32_t bf[4][2];
#pragma unroll
        for (int j = 0; j < 4; j++) {
            int nb = (j * 8 + gr) * VS + woff + kk + gc;
            bf[j][0] = __float_as_uint(Vt[nb]);
            bf[j][1] = __float_as_uint(Vt[nb + 4]);
        }
#pragma unroll
        for (int i = 0; i < 2; i++) {
            if (i == 0 && kk8 >= 6) continue;   // P cols 48+ zero for rows 0..15
            if (i == 1 && kk8 <= 1) continue;   // P cols <16 zero for rows 16..31
            uint32_t af[4];
            int rb = (i * 16 + gr) * SS + kk + gc;
            af[0] = __float_as_uint(Sw[rb]);
            af[1] = __float_as_uint(Sw[rb + 8 * SS]);
            af[2] = __float_as_uint(Sw[rb + 4]);
            af[3] = __float_as_uint(Sw[rb + 8 * SS + 4]);
#pragma unroll
            for (int j = 0; j < 4; j++)
                mma_tf32(acc2[i][j][0], acc2[i][j][1], acc2[i][j][2], acc2[i][j][3],
                         af[0], af[1], af[2], af[3], bf[j][0], bf[j][1]);
        }
    }

    const int b = bh >> 2;
    const int h = bh & 3;
#pragma unroll
    for (int i = 0; i < 2; i++) {
#pragma unroll
        for (int j = 0; j < 4; j++) {
            int d = j * 8 + gc * 2;
#pragma unroll
            for (int e2 = 0; e2 < 2; e2++) {
                int m = i * 16 + gr + e2 * 8;
                float2 v;
                v.x = acc2[i][j][e2 * 2 + 0];
                v.y = acc2[i][j][e2 * 2 + 1];
                *(float2*)(g_ctx + ((size_t)(b * Nc) + n0 + wid * 32 + m) * Ec + h * 32 + d) = v;
            }
        }
    }
}

// ---------------------------------------------------------------------------
extern "C" void kernel_launch(void* const* d_in, const int* in_sizes, int n_in,
                              void* d_out, int out_size)
{
    (void)in_sizes; (void)n_in; (void)out_size;
    const float* q  = (const float*)d_in[0];
    const float* Wq = (const float*)d_in[1];
    const float* bq = (const float*)d_in[2];
    const float* Wk = (const float*)d_in[3];
    const float* bk = (const float*)d_in[4];
    const float* Wv = (const float*)d_in[5];
    const float* bv = (const float*)d_in[6];
    const float* Wo = (const float*)d_in[7];
    const float* bo = (const float*)d_in[8];

    float* outp  = (float*)d_out;                         // (B,N,E)
    float* probs = outp + (size_t)Bc * Nc * Ec;           // (B,H,N,W)

    const int attn_smem = (128 * QS + 160 * QS + 32 * VS + 4 * 32 * SS) * 4; // 97408 B
    cudaFuncSetAttribute(attn_mma, cudaFuncAttributeMaxDynamicSharedMemorySize, attn_smem);
    cudaFuncSetAttribute(qkv_mma, cudaFuncAttributeMaxDynamicSharedMemorySize, H_TOTAL);
    cudaFuncSetAttribute(out_mma, cudaFuncAttributeMaxDynamicSharedMemorySize, H_TOTAL);

    qkv_mma<<<dim3(Mc / 128, 3), 256, H_TOTAL>>>(q, Wq, bq, Wk, bk, Wv, bv);
    attn_mma<<<dim3(Nc / 128, BHc), 128, attn_smem>>>(probs);
    out_mma<<<dim3(Mc / 128, 1), 256, H_TOTAL>>>(Wo, bo, outp);
}